// round 15
// baseline (speedup 1.0000x reference)
#include <cuda_runtime.h>
#include <cuda_bf16.h>
#include <math.h>
#include <stdint.h>

typedef unsigned long long ull;

#define E_TOTAL   65536      // B*N*K = 2*1024*32
#define EDGE_DIM  32
#define MIDC      256
#define PCOLS     768        // SPLIT_SZ = NF*MI*MO
#define W3_LD     1536
#define W3_OFF    768        // SPLIT_OFF
#define NCHUNK    4
#define KC        64

// ---- scratch (static device globals; no allocations) ----
__device__ unsigned short g_h1h[(size_t)E_TOTAL * MIDC];
__device__ unsigned short g_h1l[(size_t)E_TOTAL * MIDC];
__device__ unsigned short g_h2h[(size_t)E_TOTAL * MIDC];
__device__ unsigned short g_h2l[(size_t)E_TOTAL * MIDC];
__device__ unsigned short g_w2h[256 * 256];                // W2^T [n][k]
__device__ unsigned short g_w2l[256 * 256];
__device__ unsigned short g_w3h[768 * 256];                // W3k^T [n][k]
__device__ unsigned short g_w3l[768 * 256];
__device__ float g_tmp[(size_t)E_TOTAL * 144];             // tmp[e][j=48][d=3], 37.7MB

__device__ __forceinline__ float gelu_exact(float x) {
    return 0.5f * x * (1.0f + erff(x * 0.70710678118654752f));
}
__device__ __forceinline__ void split2(float x, unsigned short& h, unsigned short& l) {
    __nv_bfloat16 bh = __float2bfloat16_rn(x);
    float r = x - __bfloat162float(bh);
    __nv_bfloat16 bl = __float2bfloat16_rn(r);
    h = __bfloat16_as_ushort(bh);
    l = __bfloat16_as_ushort(bl);
}

// ---- packed f32x2 helpers (k1) ----
__device__ __forceinline__ ull dup2(float x) {
    ull r; asm("mov.b64 %0, {%1, %1};" : "=l"(r) : "f"(x)); return r;
}
__device__ __forceinline__ ull fma2(ull a, ull b, ull c) {
    ull d; asm("fma.rn.f32x2 %0, %1, %2, %3;" : "=l"(d) : "l"(a), "l"(b), "l"(c)); return d;
}
__device__ __forceinline__ float2 unpack2(ull v) {
    float2 f; asm("mov.b64 {%0, %1}, %2;" : "=f"(f.x), "=f"(f.y) : "l"(v)); return f;
}

// ---- warp-MMA / async helpers (baseline PTX ISA on sm_103) ----
__device__ __forceinline__ uint32_t smem_u32(const void* p) {
    uint32_t a;
    asm("{ .reg .u64 t; cvta.to.shared.u64 t, %1; cvt.u32.u64 %0, t; }" : "=r"(a) : "l"(p));
    return a;
}
__device__ __forceinline__ void ldm4(uint32_t* r, uint32_t addr) {
    asm volatile("ldmatrix.sync.aligned.m8n8.x4.shared.b16 {%0,%1,%2,%3}, [%4];"
                 : "=r"(r[0]), "=r"(r[1]), "=r"(r[2]), "=r"(r[3]) : "r"(addr));
}
__device__ __forceinline__ void mma16816(float* c, const uint32_t* a, const uint32_t* b) {
    asm volatile(
        "mma.sync.aligned.m16n8k16.row.col.f32.bf16.bf16.f32 "
        "{%0,%1,%2,%3}, {%4,%5,%6,%7}, {%8,%9}, {%0,%1,%2,%3};"
        : "+f"(c[0]), "+f"(c[1]), "+f"(c[2]), "+f"(c[3])
        : "r"(a[0]), "r"(a[1]), "r"(a[2]), "r"(a[3]), "r"(b[0]), "r"(b[1]));
}
__device__ __forceinline__ void cpa16(uint32_t dst, const void* src) {
    asm volatile("cp.async.cg.shared.global [%0], [%1], 16;" :: "r"(dst), "l"(src));
}
#define CP_COMMIT() asm volatile("cp.async.commit_group;" ::: "memory")
__device__ __forceinline__ uint32_t sw128(uint32_t bo) {
    return bo ^ ((bo >> 3) & 0x70);
}

// ============================================================
// Kernel 0: transpose + split weights to bf16 hi/lo, K-major
// ============================================================
__global__ __launch_bounds__(256) void k_prep_w(
    const float* __restrict__ W2, const float* __restrict__ W3)
{
    int idx = blockIdx.x * 256 + threadIdx.x;
    if (idx < 256 * 256) {
        int k = idx >> 8, n = idx & 255;
        unsigned short h, l;
        split2(W2[k * 256 + n], h, l);
        g_w2h[n * 256 + k] = h;
        g_w2l[n * 256 + k] = l;
    } else {
        int j = idx - 256 * 256;
        int k = j / 768, n = j % 768;
        unsigned short h, l;
        split2(W3[k * W3_LD + W3_OFF + n], h, l);
        g_w3h[n * 256 + k] = h;
        g_w3l[n * 256 + k] = l;
    }
}

// ============================================================
// Kernel 1: h1 = gelu(edges[E,32] @ W1 + b1) -> bf16 hi/lo
// ============================================================
__global__ __launch_bounds__(256) void k1_mlp1(
    const float* __restrict__ edges, const float* __restrict__ W1,
    const float* __restrict__ b1)
{
    __shared__ float esT[32][64];
    __shared__ float W1s[32][256];
    const int tid = threadIdx.x;
    const long e0 = (long)blockIdx.x * 64;

    #pragma unroll
    for (int i = 0; i < 8; i++) {
        int flat = tid + i * 256;
        esT[flat & 31][flat >> 5] = edges[e0 * EDGE_DIM + flat];
    }
    #pragma unroll
    for (int i = 0; i < 32; i++) {
        int flat = tid + i * 256;
        W1s[flat >> 8][flat & 255] = W1[flat];
    }
    __syncthreads();

    const int m = tid;
    ull wd[EDGE_DIM];
    #pragma unroll
    for (int k = 0; k < EDGE_DIM; k++) wd[k] = dup2(W1s[k][m]);
    const ull binit = dup2(b1[m]);

    for (int p = 0; p < 32; p++) {
        ull acc = binit;
        #pragma unroll
        for (int k = 0; k < EDGE_DIM; k++) {
            ull a2 = reinterpret_cast<const ull*>(&esT[k][0])[p];
            acc = fma2(a2, wd[k], acc);
        }
        float2 v = unpack2(acc);
        unsigned short h, l;
        size_t o0 = (size_t)(e0 + 2 * p) * MIDC + m;
        split2(gelu_exact(v.x), h, l);
        g_h1h[o0] = h; g_h1l[o0] = l;
        split2(gelu_exact(v.y), h, l);
        g_h1h[o0 + MIDC] = h; g_h1l[o0 + MIDC] = l;
    }
}

// ============================================================
// Kernel T: tmp[e*144 + i*9 + z] = sum_din feats[e,i,din]*basis[e,din,z]
// ============================================================
__global__ __launch_bounds__(256) void k_tmp(
    const float* __restrict__ feats, const float* __restrict__ basis)
{
    int idx = blockIdx.x * 256 + threadIdx.x;   // E*144
    int e = idx / 144;
    int f = idx % 144;
    int i = f / 9;
    int z = f % 9;
    const float* fp = feats + (size_t)e * 48 + i * 3;
    const float* bp = basis + (size_t)e * 27 + z;
    float v = fp[0] * bp[0] + fp[1] * bp[9] + fp[2] * bp[18];
    g_tmp[idx] = v;
}

// ============================================================
// bf16-split warp-MMA GEMM, cp.async double-buffered.
//   Inner loop issues the 3 split-products as separate PASSES so that
//   accumulator reuse distance is ~16 MMAs (kills HMMA RAW stalls).
// ============================================================
template <int NTILE, bool GELU, bool FUSE>
__global__ __launch_bounds__(256) void k_mma_gemm(
    const unsigned short* __restrict__ Ah, const unsigned short* __restrict__ Al,
    const unsigned short* __restrict__ Wh, const unsigned short* __restrict__ Wl,
    const float* __restrict__ bias,
    unsigned short* __restrict__ Ch, unsigned short* __restrict__ Cl,
    const float* __restrict__ tmpg, float* __restrict__ outg)
{
    constexpr int SA    = 128 * 128;           // one A tile (bytes)
    constexpr int SB    = NTILE * 128;         // one B tile (bytes)
    constexpr int CHUNK = 2 * SA + 2 * SB;     // AH AL BH BL
    constexpr int NG    = NTILE / 16;          // n8-groups per warp
    constexpr int NP    = NTILE / 32;          // 16-col B ldmatrix groups

    extern __shared__ char sm[];
    const uint32_t smb = smem_u32(sm);
    const int tid = threadIdx.x;
    const int wid = tid >> 5;
    const int l   = tid & 31;
    const int wm  = wid >> 1;
    const int wn  = wid & 1;
    const long e0 = (long)blockIdx.y * 128;
    const int n0  = blockIdx.x * NTILE;
    float* bias_s = reinterpret_cast<float*>(sm + 2 * CHUNK);

    if (GELU && tid < NTILE) bias_s[tid] = bias[n0 + tid];

    // ---- staging geometry (16B segs, swizzled) ----
    const int srow = tid >> 1;
    const int sseg = tid & 1;
    const size_t gA = (size_t)(e0 + srow) * 256 + sseg * 32;
    const uint32_t swA[4] = {
        sw128((uint32_t)srow * 128 + sseg * 64 + 0),
        sw128((uint32_t)srow * 128 + sseg * 64 + 16),
        sw128((uint32_t)srow * 128 + sseg * 64 + 32),
        sw128((uint32_t)srow * 128 + sseg * 64 + 48)};

    auto stage = [&](int c, int buf) {
        const int k0 = c * KC;
        const uint32_t base = smb + buf * CHUNK;
        #pragma unroll
        for (int i = 0; i < 4; i++) {
            cpa16(base + swA[i],      Ah + gA + k0 + i * 8);
            cpa16(base + SA + swA[i], Al + gA + k0 + i * 8);
        }
        #pragma unroll
        for (int i = 0; i < NTILE * 8 / 256; i++) {
            int s = tid + i * 256;
            int row = s >> 3, sc = s & 7;
            uint32_t so = sw128((uint32_t)row * 128 + sc * 16);
            const size_t gB = (size_t)(n0 + row) * 256 + k0 + sc * 8;
            cpa16(base + 2 * SA + so,      Wh + gB);
            cpa16(base + 2 * SA + SB + so, Wl + gB);
        }
    };

    // ---- ldmatrix per-thread offsets (pre-swizzle) ----
    const uint32_t aro  = (uint32_t)(wm * 32 + (l & 15)) * 128 + ((l >> 4) * 16);
    const uint32_t aro1 = aro + 16 * 128;
    const int brow_in16 = ((l & 16) >> 1) + (l & 7);
    const uint32_t bko  = (l & 8) ? 16u : 0u;
    uint32_t bro[NP];
    #pragma unroll
    for (int p = 0; p < NP; p++)
        bro[p] = (uint32_t)(wn * (NTILE / 2) + p * 16 + brow_in16) * 128 + bko;

    float acc[2][NG][4];
    #pragma unroll
    for (int mi = 0; mi < 2; mi++)
        #pragma unroll
        for (int ng = 0; ng < NG; ng++)
            #pragma unroll
            for (int t = 0; t < 4; t++) acc[mi][ng][t] = 0.0f;

    stage(0, 0);
    CP_COMMIT();

    for (int c = 0; c < NCHUNK; c++) {
        if (c < NCHUNK - 1) {
            stage(c + 1, (c + 1) & 1);
            CP_COMMIT();
            asm volatile("cp.async.wait_group 1;" ::: "memory");
        } else {
            asm volatile("cp.async.wait_group 0;" ::: "memory");
        }
        __syncthreads();

        const uint32_t base = smb + (c & 1) * CHUNK;
        #pragma unroll
        for (int ks = 0; ks < 4; ks++) {
            const uint32_t kb = ks * 32;
            // ---- preload ALL fragments for this k-step ----
            uint32_t ahf[2][4], alf[2][4];
            uint32_t bhf[NP][4], blf[NP][4];
            ldm4(ahf[0], base + sw128(aro + kb));
            ldm4(ahf[1], base + sw128(aro1 + kb));
            ldm4(alf[0], base + SA + sw128(aro + kb));
            ldm4(alf[1], base + SA + sw128(aro1 + kb));
            #pragma unroll
            for (int p = 0; p < NP; p++) {
                ldm4(bhf[p], base + 2 * SA + sw128(bro[p] + kb));
                ldm4(blf[p], base + 2 * SA + SB + sw128(bro[p] + kb));
            }
            // ---- pass 1: Ah @ Bh  (all distinct accumulators) ----
            #pragma unroll
            for (int p = 0; p < NP; p++)
                #pragma unroll
                for (int mi = 0; mi < 2; mi++) {
                    mma16816(acc[mi][2 * p],     ahf[mi], bhf[p]);
                    mma16816(acc[mi][2 * p + 1], ahf[mi], bhf[p] + 2);
                }
            // ---- pass 2: Ah @ Bl ----
            #pragma unroll
            for (int p = 0; p < NP; p++)
                #pragma unroll
                for (int mi = 0; mi < 2; mi++) {
                    mma16816(acc[mi][2 * p],     ahf[mi], blf[p]);
                    mma16816(acc[mi][2 * p + 1], ahf[mi], blf[p] + 2);
                }
            // ---- pass 3: Al @ Bh ----
            #pragma unroll
            for (int p = 0; p < NP; p++)
                #pragma unroll
                for (int mi = 0; mi < 2; mi++) {
                    mma16816(acc[mi][2 * p],     alf[mi], bhf[p]);
                    mma16816(acc[mi][2 * p + 1], alf[mi], bhf[p] + 2);
                }
        }
        __syncthreads();
    }

    if (GELU) {
        const int crow = wm * 32 + (l >> 2);
        const int ccol = wn * (NTILE / 2) + 2 * (l & 3);
        #pragma unroll
        for (int mi = 0; mi < 2; mi++) {
            #pragma unroll
            for (int ng = 0; ng < NG; ng++) {
                const int col = ccol + ng * 8;
                const float* cf = acc[mi][ng];
                #pragma unroll
                for (int half = 0; half < 2; half++) {
                    const long e = e0 + crow + mi * 16 + half * 8;
                    float x0 = gelu_exact(cf[2 * half + 0] + bias_s[col]);
                    float x1 = gelu_exact(cf[2 * half + 1] + bias_s[col + 1]);
                    unsigned short h0, l0, h1, l1;
                    split2(x0, h0, l0);
                    split2(x1, h1, l1);
                    *reinterpret_cast<uint32_t*>(Ch + (size_t)e * MIDC + n0 + col) =
                        (uint32_t)h0 | ((uint32_t)h1 << 16);
                    *reinterpret_cast<uint32_t*>(Cl + (size_t)e * MIDC + n0 + col) =
                        (uint32_t)l0 | ((uint32_t)l1 << 16);
                }
            }
        }
    }
    if (FUSE) {
        // ---- fused k4: stage tmp[e0..e0+127][144], contract, reduce ----
        float* tsm = reinterpret_cast<float*>(sm);
        {
            const float4* tg = reinterpret_cast<const float4*>(tmpg + e0 * 144);
            float4* ts4 = reinterpret_cast<float4*>(sm);
            #pragma unroll
            for (int i = 0; i < 18; i++) ts4[tid + i * 256] = tg[tid + i * 256];
        }
        __syncthreads();

        float pout[4][3];
        #pragma unroll
        for (int r = 0; r < 4; r++)
            #pragma unroll
            for (int d = 0; d < 3; d++) pout[r][d] = 0.0f;

        const int rbase = wm * 32 + (l >> 2);
        #pragma unroll
        for (int mi = 0; mi < 2; mi++) {
            #pragma unroll
            for (int half = 0; half < 2; half++) {
                const int el = rbase + mi * 16 + half * 8;
                const float* te = tsm + el * 144;
                #pragma unroll
                for (int ng = 0; ng < NG; ng++) {
                    #pragma unroll
                    for (int t = 0; t < 2; t++) {
                        const int j = 2 * (l & 3) + ng * 8 + t;
                        const float rp = acc[mi][ng][2 * half + t];
                        pout[mi * 2 + half][0] = fmaf(rp, te[j * 3 + 0], pout[mi * 2 + half][0]);
                        pout[mi * 2 + half][1] = fmaf(rp, te[j * 3 + 1], pout[mi * 2 + half][1]);
                        pout[mi * 2 + half][2] = fmaf(rp, te[j * 3 + 2], pout[mi * 2 + half][2]);
                    }
                }
            }
        }
        #pragma unroll
        for (int r = 0; r < 4; r++)
            #pragma unroll
            for (int d = 0; d < 3; d++) {
                float v = pout[r][d];
                v += __shfl_xor_sync(0xFFFFFFFFu, v, 1);
                v += __shfl_xor_sync(0xFFFFFFFFu, v, 2);
                pout[r][d] = v;
            }
        if ((l & 3) == 0) {
            const int og = blockIdx.x * 2 + wn;
            #pragma unroll
            for (int mi = 0; mi < 2; mi++)
                #pragma unroll
                for (int half = 0; half < 2; half++) {
                    const long e = e0 + rbase + mi * 16 + half * 8;
                    float* op = outg + e * 48 + og * 3;
                    op[0] = pout[mi * 2 + half][0];
                    op[1] = pout[mi * 2 + half][1];
                    op[2] = pout[mi * 2 + half][2];
                }
        }
    }
}

// ============================================================
extern "C" void kernel_launch(void* const* d_in, const int* in_sizes, int n_in,
                              void* d_out, int out_size)
{
    const float* edges = (const float*)d_in[0];
    const float* feats = (const float*)d_in[1];
    const float* basis = (const float*)d_in[2];
    const float* W1    = (const float*)d_in[3];
    const float* b1    = (const float*)d_in[4];
    const float* W2    = (const float*)d_in[5];
    const float* b2    = (const float*)d_in[6];
    const float* W3    = (const float*)d_in[7];
    float* out = (float*)d_out;

    unsigned short *h1h, *h1l, *h2h, *h2l, *w2h, *w2l, *w3h, *w3l;
    float* tmpp;
    cudaGetSymbolAddress((void**)&h1h, g_h1h);
    cudaGetSymbolAddress((void**)&h1l, g_h1l);
    cudaGetSymbolAddress((void**)&h2h, g_h2h);
    cudaGetSymbolAddress((void**)&h2l, g_h2l);
    cudaGetSymbolAddress((void**)&w2h, g_w2h);
    cudaGetSymbolAddress((void**)&w2l, g_w2l);
    cudaGetSymbolAddress((void**)&w3h, g_w3h);
    cudaGetSymbolAddress((void**)&w3l, g_w3l);
    cudaGetSymbolAddress((void**)&tmpp, g_tmp);

    const int SM2 = 2 * (2 * 16384 + 2 * 16384) + 512;
    const int SM3 = 2 * (2 * 16384 + 2 * 12288);
    cudaFuncSetAttribute((const void*)k_mma_gemm<128, true, false>,
                         cudaFuncAttributeMaxDynamicSharedMemorySize, SM2);
    cudaFuncSetAttribute((const void*)k_mma_gemm<96, false, true>,
                         cudaFuncAttributeMaxDynamicSharedMemorySize, SM3);

    // 0) weight transpose + bf16 split
    k_prep_w<<<1024, 256>>>(W2, W3);

    // 1) h1 = gelu(edges @ W1 + b1) -> bf16 hi/lo
    k1_mlp1<<<E_TOTAL / 64, 256>>>(edges, W1, b1);

    // T) tmp = feats @ basis
    k_tmp<<<E_TOTAL * 144 / 256, 256>>>(feats, basis);

    // 2) h2 = gelu(h1 @ W2 + b2) -> bf16 hi/lo
    k_mma_gemm<128, true, false><<<dim3(MIDC / 128, E_TOTAL / 128), 256, SM2>>>(
        h1h, h1l, w2h, w2l, b2, h2h, h2l, nullptr, nullptr);

    // 3) out = (h2 @ W3k) contracted with tmp  (rp never hits DRAM)
    k_mma_gemm<96, false, true><<<dim3(PCOLS / 96, E_TOTAL / 128), 256, SM3>>>(
        h2h, h2l, w3h, w3l, nullptr, nullptr, nullptr, tmpp, out);
}